// round 7
// baseline (speedup 1.0000x reference)
#include <cuda_runtime.h>
#include <cuda_bf16.h>
#include <math.h>
#include <stdint.h>

#define Bq 64
#define TSq 300
#define TDq 180
#define Fq 128
#define Hq 512
#define Lq 4
#define Gq 2048   // 4*H

// ---------------- static device scratch (no runtime allocation) ----------------
__device__ float g_xp[(size_t)2 * Bq * TSq * Gq];
__device__ float g_X0[(size_t)Bq * TSq * 1024];
__device__ float g_X1[(size_t)Bq * TSq * 1024];
__device__ float g_dcat[(size_t)Bq * TDq * 640];
__device__ float g_hwork[2][2 * Bq * Hq];
__device__ float g_cwork[2 * Bq * Hq];
__device__ float g_hs[Lq * Bq * 1024];
__device__ float g_cs[Lq * Bq * 1024];
__device__ float g_h0[Lq * Bq * Hq];
__device__ float g_c0[Lq * Bq * Hq];
__device__ unsigned g_barCnt[8];
__device__ unsigned g_barRoot;
__device__ unsigned g_barGen;
// bf16 split buffers for tensor-core GEMMs
__device__ __nv_bfloat16 g_Ah[(size_t)Bq * TSq * 1024];
__device__ __nv_bfloat16 g_Al[(size_t)Bq * TSq * 1024];
__device__ __nv_bfloat16 g_Wh[(size_t)2 * Gq * 1024];
__device__ __nv_bfloat16 g_Wl[(size_t)2 * Gq * 1024];

// -------- mma.sync / ldmatrix / cp.async helpers (compute_103-safe) -----
__device__ __forceinline__ uint32_t smem_u32(const void* p) {
    uint32_t a;
    asm("{ .reg .u64 t; cvta.to.shared.u64 t, %1; cvt.u32.u64 %0, t; }" : "=r"(a) : "l"(p));
    return a;
}
#define LDM_X4(r0, r1, r2, r3, addr) \
    asm volatile("ldmatrix.sync.aligned.m8n8.x4.shared.b16 {%0,%1,%2,%3}, [%4];" \
        : "=r"(r0), "=r"(r1), "=r"(r2), "=r"(r3) : "r"(addr))
#define LDM_X2(r0, r1, addr) \
    asm volatile("ldmatrix.sync.aligned.m8n8.x2.shared.b16 {%0,%1}, [%2];" \
        : "=r"(r0), "=r"(r1) : "r"(addr))
#define MMA_BF16(c0, c1, c2, c3, a0, a1, a2, a3, b0, b1) \
    asm volatile("mma.sync.aligned.m16n8k16.row.col.f32.bf16.bf16.f32 " \
        "{%0,%1,%2,%3}, {%4,%5,%6,%7}, {%8,%9}, {%0,%1,%2,%3};" \
        : "+f"(c0), "+f"(c1), "+f"(c2), "+f"(c3) \
        : "r"(a0), "r"(a1), "r"(a2), "r"(a3), "r"(b0), "r"(b1))
#define CPA16(dst, src) \
    asm volatile("cp.async.cg.shared.global [%0], [%1], 16;" :: "r"(dst), "l"(src))
#define CPA_COMMIT() asm volatile("cp.async.commit_group;" ::: "memory")
#define CPA_WAIT(n)  asm volatile("cp.async.wait_group %0;" :: "n"(n) : "memory")

__device__ __forceinline__ uint32_t bf2pack(float fhi, float flo) {
    uint32_t r;
    asm("cvt.rn.bf16x2.f32 %0, %1, %2;" : "=r"(r) : "f"(fhi), "f"(flo));
    return r;
}
__device__ __forceinline__ float trunc_hi(float f) {
    return __uint_as_float(__float_as_uint(f) & 0xFFFF0000u);
}
__device__ __forceinline__ void split8(float4 a, float4 b, uint4& hi, uint4& lo) {
    hi.x = __byte_perm(__float_as_uint(a.x), __float_as_uint(a.y), 0x7632);
    hi.y = __byte_perm(__float_as_uint(a.z), __float_as_uint(a.w), 0x7632);
    hi.z = __byte_perm(__float_as_uint(b.x), __float_as_uint(b.y), 0x7632);
    hi.w = __byte_perm(__float_as_uint(b.z), __float_as_uint(b.w), 0x7632);
    lo.x = bf2pack(a.y - trunc_hi(a.y), a.x - trunc_hi(a.x));
    lo.y = bf2pack(a.w - trunc_hi(a.w), a.z - trunc_hi(a.z));
    lo.z = bf2pack(b.y - trunc_hi(b.y), b.x - trunc_hi(b.x));
    lo.w = bf2pack(b.w - trunc_hi(b.w), b.z - trunc_hi(b.z));
}

// ---------------------------------------------------------------------------
// two-level software grid barrier (gridDim.x == 128, all blocks co-resident)
// 8 group counters x 16 arrivals each, then root (8 arrivals) flips gen.
// ---------------------------------------------------------------------------
__device__ __forceinline__ void gridBarrier()
{
    __syncthreads();
    if (threadIdx.x == 0) {
        const unsigned gen = *((volatile unsigned*)&g_barGen);
        __threadfence();                               // release prior writes
        const unsigned grp = blockIdx.x & 7u;          // 16 members per group
        if (atomicAdd(&g_barCnt[grp], 1u) == 15u) {
            atomicExch(&g_barCnt[grp], 0u);
            __threadfence();
            if (atomicAdd(&g_barRoot, 1u) == 7u) {
                atomicExch(&g_barRoot, 0u);
                __threadfence();
                atomicAdd(&g_barGen, 1u);
            }
        }
        while (*((volatile unsigned*)&g_barGen) == gen) { __nanosleep(64); }
        __threadfence();                               // acquire
    }
    __syncthreads();
}

// ---------------------------------------------------------------------------
// fp32 -> bf16 hi/lo split (elementwise), n % 4 == 0
// ---------------------------------------------------------------------------
__global__ void conv_split(const float* __restrict__ in, __nv_bfloat16* __restrict__ hi,
                           __nv_bfloat16* __restrict__ lo, size_t n)
{
    const size_t i = ((size_t)blockIdx.x * 256 + threadIdx.x) * 4;
    if (i >= n) return;
    const float4 v = *(const float4*)(in + i);
    __nv_bfloat16 h0 = __float2bfloat16(v.x), h1 = __float2bfloat16(v.y);
    __nv_bfloat16 h2 = __float2bfloat16(v.z), h3 = __float2bfloat16(v.w);
    __nv_bfloat16 l0 = __float2bfloat16(v.x - __bfloat162float(h0));
    __nv_bfloat16 l1 = __float2bfloat16(v.y - __bfloat162float(h1));
    __nv_bfloat16 l2 = __float2bfloat16(v.z - __bfloat162float(h2));
    __nv_bfloat16 l3 = __float2bfloat16(v.w - __bfloat162float(h3));
    __nv_bfloat162 hp0(h0, h1), hp1(h2, h3), lp0(l0, l1), lp1(l2, l3);
    *(uint2*)(hi + i) = make_uint2(*(uint32_t*)&hp0, *(uint32_t*)&hp1);
    *(uint2*)(lo + i) = make_uint2(*(uint32_t*)&lp0, *(uint32_t*)&lp1);
}

// ---------------------------------------------------------------------------
// Split-bf16 tensor-core GEMM via mma.sync: C[M,N] = op(A[M,K] @ W[N,K]^T + b)
// D = Ah*Wh + Ah*Wl + Al*Wh (fp32 accum). 128x128 CTA tile, 8 warps (2x4),
// warp tile 64x32 via m16n8k16. K chunks of 32, 3-stage cp.async pipeline.
// act=1 applies tanh. M%128==0, N%128==0, K%32==0, K>=96.
// ---------------------------------------------------------------------------
#define MMA_TILE_B   8192                   // one 128x32 bf16 tile
#define MMA_BUF_B    (4 * MMA_TILE_B)       // Ah|Al|Wh|Wl per stage = 32KB
#define MMA_STAGES   3
#define MMA_SMEM_B   (MMA_STAGES * MMA_BUF_B)  // 96KB

__global__ __launch_bounds__(256, 2)
void mma_xp(const __nv_bfloat16* __restrict__ Ah, const __nv_bfloat16* __restrict__ Al,
            const __nv_bfloat16* __restrict__ Wh, const __nv_bfloat16* __restrict__ Wl,
            const float* __restrict__ bias, float* __restrict__ C,
            int M, int N, int K, size_t wZ, size_t bZ, size_t cZ, int act)
{
    extern __shared__ __align__(128) char smem[];
    const uint32_t sbase = smem_u32(smem);

    Wh   += blockIdx.z * wZ;
    Wl   += blockIdx.z * wZ;
    bias += blockIdx.z * bZ;
    C    += blockIdx.z * cZ;
    const int n0 = blockIdx.x * 128;
    const int m0 = blockIdx.y * 128;

    const int tid  = threadIdx.x;
    const int lane = tid & 31;
    const int warp = tid >> 5;
    const int wm = warp >> 2;
    const int wn = warp & 3;

    float acc[4][4][4];
#pragma unroll
    for (int i = 0; i < 4; i++)
#pragma unroll
        for (int j = 0; j < 4; j++)
#pragma unroll
            for (int q = 0; q < 4; q++) acc[i][j][q] = 0.f;

    const int r0g = tid >> 2,        g0 = tid & 3;
    const int r1g = (tid + 256) >> 2, g1 = (tid + 256) & 3;
    const uint32_t so0 = (uint32_t)(r0g * 64 + ((g0 ^ (r0g & 3)) << 4));
    const uint32_t so1 = (uint32_t)(r1g * 64 + ((g1 ^ (r1g & 3)) << 4));

    const int arow = wm * 64 + (lane & 15);
    const int aswz = arow & 3;
    const int agoff = lane >> 4;
    const int brow = wn * 32 + (lane & 7);
    const int bgoff = (lane >> 3) & 1;
    const int bnt   = (lane >> 4);

    const int nch = K >> 5;

#define ISSUE_CHUNK(c) do { \
    const uint32_t _buf = sbase + (uint32_t)((c) % MMA_STAGES) * MMA_BUF_B; \
    const size_t _k0 = (size_t)((c) << 5); \
    CPA16(_buf + 0 * MMA_TILE_B + so0, Ah + (size_t)(m0 + r0g) * K + _k0 + g0 * 8); \
    CPA16(_buf + 1 * MMA_TILE_B + so0, Al + (size_t)(m0 + r0g) * K + _k0 + g0 * 8); \
    CPA16(_buf + 2 * MMA_TILE_B + so0, Wh + (size_t)(n0 + r0g) * K + _k0 + g0 * 8); \
    CPA16(_buf + 3 * MMA_TILE_B + so0, Wl + (size_t)(n0 + r0g) * K + _k0 + g0 * 8); \
    CPA16(_buf + 0 * MMA_TILE_B + so1, Ah + (size_t)(m0 + r1g) * K + _k0 + g1 * 8); \
    CPA16(_buf + 1 * MMA_TILE_B + so1, Al + (size_t)(m0 + r1g) * K + _k0 + g1 * 8); \
    CPA16(_buf + 2 * MMA_TILE_B + so1, Wh + (size_t)(n0 + r1g) * K + _k0 + g1 * 8); \
    CPA16(_buf + 3 * MMA_TILE_B + so1, Wl + (size_t)(n0 + r1g) * K + _k0 + g1 * 8); \
} while (0)

    ISSUE_CHUNK(0); CPA_COMMIT();
    ISSUE_CHUNK(1); CPA_COMMIT();

    for (int c = 0; c < nch; c++) {
        if (c + 2 < nch) { ISSUE_CHUNK(c + 2); CPA_COMMIT(); CPA_WAIT(2); }
        else if (c + 1 < nch) { CPA_WAIT(1); }
        else { CPA_WAIT(0); }
        __syncthreads();

        const uint32_t buf = sbase + (uint32_t)(c % MMA_STAGES) * MMA_BUF_B;
        const uint32_t aH = buf + 0 * MMA_TILE_B;
        const uint32_t aL = buf + 1 * MMA_TILE_B;
        const uint32_t wH = buf + 2 * MMA_TILE_B;
        const uint32_t wL = buf + 3 * MMA_TILE_B;

#pragma unroll
        for (int ks = 0; ks < 2; ks++) {
            uint32_t af[4][4], bh[4][2], bl[4][2];
#pragma unroll
            for (int mt = 0; mt < 4; mt++) {
                const int rA = arow + mt * 16;
                const uint32_t ad = aH + (uint32_t)(rA * 64 + (((ks * 2 + agoff) ^ aswz) << 4));
                LDM_X4(af[mt][0], af[mt][1], af[mt][2], af[mt][3], ad);
            }
#pragma unroll
            for (int p = 0; p < 2; p++) {
                const int rB = brow + (p * 2 + bnt) * 8;
                const uint32_t off = (uint32_t)(rB * 64 + (((ks * 2 + bgoff) ^ (rB & 3)) << 4));
                LDM_X4(bh[p * 2][0], bh[p * 2][1], bh[p * 2 + 1][0], bh[p * 2 + 1][1], wH + off);
                LDM_X4(bl[p * 2][0], bl[p * 2][1], bl[p * 2 + 1][0], bl[p * 2 + 1][1], wL + off);
            }
#pragma unroll
            for (int mt = 0; mt < 4; mt++)
#pragma unroll
                for (int nt = 0; nt < 4; nt++) {
                    MMA_BF16(acc[mt][nt][0], acc[mt][nt][1], acc[mt][nt][2], acc[mt][nt][3],
                             af[mt][0], af[mt][1], af[mt][2], af[mt][3],
                             bh[nt][0], bh[nt][1]);
                    MMA_BF16(acc[mt][nt][0], acc[mt][nt][1], acc[mt][nt][2], acc[mt][nt][3],
                             af[mt][0], af[mt][1], af[mt][2], af[mt][3],
                             bl[nt][0], bl[nt][1]);
                }
#pragma unroll
            for (int mt = 0; mt < 4; mt++) {
                const int rA = arow + mt * 16;
                const uint32_t ad = aL + (uint32_t)(rA * 64 + (((ks * 2 + agoff) ^ aswz) << 4));
                LDM_X4(af[mt][0], af[mt][1], af[mt][2], af[mt][3], ad);
            }
#pragma unroll
            for (int mt = 0; mt < 4; mt++)
#pragma unroll
                for (int nt = 0; nt < 4; nt++)
                    MMA_BF16(acc[mt][nt][0], acc[mt][nt][1], acc[mt][nt][2], acc[mt][nt][3],
                             af[mt][0], af[mt][1], af[mt][2], af[mt][3],
                             bh[nt][0], bh[nt][1]);
        }
        __syncthreads();
    }

    const int mE = m0 + wm * 64 + (lane >> 2);
    const int nE = n0 + wn * 32 + (lane & 3) * 2;
#pragma unroll
    for (int mt = 0; mt < 4; mt++) {
#pragma unroll
        for (int nt = 0; nt < 4; nt++) {
            const int m = mE + mt * 16;
            const int n = nE + nt * 8;
            const float b0 = bias[n], b1 = bias[n + 1];
            float v00 = acc[mt][nt][0] + b0, v01 = acc[mt][nt][1] + b1;
            float v10 = acc[mt][nt][2] + b0, v11 = acc[mt][nt][3] + b1;
            if (act) { v00 = tanhf(v00); v01 = tanhf(v01); v10 = tanhf(v10); v11 = tanhf(v11); }
            *(float2*)(C + (size_t)m * N + n)       = make_float2(v00, v01);
            *(float2*)(C + (size_t)(m + 8) * N + n) = make_float2(v10, v11);
        }
    }
}

// ---------------------------------------------------------------------------
// Persistent LSTM layer with tensor-core recurrence (round-6 structure,
// two-level barrier). NBL=32: encoder; NBL=16: decoder. grid=128 always.
// ---------------------------------------------------------------------------
template<int NBL>
__global__ __launch_bounds__(256)
void lstm_persist(const float* __restrict__ xp, const float* __restrict__ Whh,
                  const float* __restrict__ h0, const float* __restrict__ c0,
                  float* __restrict__ hA, float* __restrict__ hB,
                  float* __restrict__ cSt, float* __restrict__ y,
                  float* __restrict__ hFin, float* __restrict__ cFin,
                  int T, int revDir1, int yStride, int yDirMult)
{
    constexpr int U    = NBL / 4;
    constexpr int USH  = (NBL == 32) ? 3 : 2;
    constexpr int WNT  = NBL / 16;
    constexpr int GSs  = NBL + 2;
    constexpr uint32_t S_AH = 0;
    constexpr uint32_t S_AL = 64 * 1024;
    constexpr uint32_t S_BH = 128 * 1024;
    constexpr uint32_t S_BL = S_BH + NBL * 1024;
    constexpr uint32_t S_GS = S_BL + NBL * 1024;

    extern __shared__ __align__(128) char smem[];
    const uint32_t sb = smem_u32(smem);
    float* Gs = (float*)(smem + S_GS);

    const int tid  = threadIdx.x;
    const int lane = tid & 31;
    const int warp = tid >> 5;
    const int mi = warp >> 1;
    const int nh = warp & 1;

    int dir, u0;
    if (NBL == 32) { dir = blockIdx.x >> 6; u0 = (blockIdx.x & 63) * 8; }
    else           { dir = 0;               u0 = blockIdx.x * 4; }

    const float* xpd = xp  + (size_t)dir * Bq * T * Gq;
    const float* Wd  = Whh + (size_t)dir * Gq * Hq;
    float* hArr[2] = { hA + dir * Bq * Hq, hB + dir * Bq * Hq };
    float* cD = cSt + dir * Bq * Hq;

    for (int i = tid; i < NBL * 64; i += 256) {
        const int row = i >> 6;
        const int g   = i & 63;
        const int gate = row >> (USH - 1) >> 1;
        const int uu   = row & (U - 1);
        const int wrow = (gate << 9) + u0 + uu;
        const float4 va = *(const float4*)(Wd + (size_t)wrow * Hq + g * 8);
        const float4 vb = *(const float4*)(Wd + (size_t)wrow * Hq + g * 8 + 4);
        uint4 hi, lo;
        split8(va, vb, hi, lo);
        const uint32_t so = (uint32_t)(row * 1024 + ((g ^ (row & 7)) << 4));
        *(uint4*)(smem + S_BH + so) = hi;
        *(uint4*)(smem + S_BL + so) = lo;
    }

    for (int i = tid; i < Bq * U; i += 256) {
        const int b = i >> USH, uu = i & (U - 1), u = u0 + uu;
        hArr[0][b * Hq + u] = h0 ? h0[b * Hq + u] : 0.f;
        cD        [b * Hq + u] = c0 ? c0[b * Hq + u] : 0.f;
    }
    gridBarrier();

    const int rowA = (lane & 15);
    const int agoff = lane >> 4;
    const int bnt   = lane >> 4;
    const int bgoff = (lane >> 3) & 1;

    int ping = 0;
    for (int t = 0; t < T; t++) {
        const int tt = (dir == 1 && revDir1) ? (T - 1 - t) : t;
        const float* hI = hArr[ping];
        float*       hO = hArr[ping ^ 1];

#pragma unroll
        for (int it = 0; it < 16; it++) {
            const int slot = tid + it * 256;
            const int row = slot >> 6, g = slot & 63;
            const float4 va = __ldcg((const float4*)(hI + (size_t)row * Hq + g * 8));
            const float4 vb = __ldcg((const float4*)(hI + (size_t)row * Hq + g * 8 + 4));
            uint4 hi, lo;
            split8(va, vb, hi, lo);
            const uint32_t so = (uint32_t)(row * 1024 + ((g ^ (row & 7)) << 4));
            *(uint4*)(smem + S_AH + so) = hi;
            *(uint4*)(smem + S_AL + so) = lo;
        }
        __syncthreads();

        float acc[WNT][4];
#pragma unroll
        for (int nt = 0; nt < WNT; nt++)
#pragma unroll
            for (int q = 0; q < 4; q++) acc[nt][q] = 0.f;

#pragma unroll 4
        for (int ks = 0; ks < 32; ks++) {
            const int rA = mi * 16 + rowA;
            const uint32_t aoff = (uint32_t)(rA * 1024 + (((ks * 2 + agoff) ^ (rA & 7)) << 4));
            uint32_t ah[4], al[4], bh[2 * WNT], bl[2 * WNT];
            LDM_X4(ah[0], ah[1], ah[2], ah[3], sb + S_AH + aoff);
            LDM_X4(al[0], al[1], al[2], al[3], sb + S_AL + aoff);
            if (WNT == 2) {
                const int rB = nh * 16 + bnt * 8 + (lane & 7);
                const uint32_t boff = (uint32_t)(rB * 1024 + (((ks * 2 + bgoff) ^ (rB & 7)) << 4));
                LDM_X4(bh[0], bh[1], bh[2], bh[3], sb + S_BH + boff);
                LDM_X4(bl[0], bl[1], bl[2], bl[3], sb + S_BL + boff);
            } else {
                const int rB = nh * 8 + (lane & 7);
                const uint32_t boff = (uint32_t)(rB * 1024 + (((ks * 2 + bgoff) ^ (rB & 7)) << 4));
                LDM_X2(bh[0], bh[1], sb + S_BH + boff);
                LDM_X2(bl[0], bl[1], sb + S_BL + boff);
            }
#pragma unroll
            for (int nt = 0; nt < WNT; nt++) {
                MMA_BF16(acc[nt][0], acc[nt][1], acc[nt][2], acc[nt][3],
                         ah[0], ah[1], ah[2], ah[3], bh[nt * 2], bh[nt * 2 + 1]);
                MMA_BF16(acc[nt][0], acc[nt][1], acc[nt][2], acc[nt][3],
                         ah[0], ah[1], ah[2], ah[3], bl[nt * 2], bl[nt * 2 + 1]);
                MMA_BF16(acc[nt][0], acc[nt][1], acc[nt][2], acc[nt][3],
                         al[0], al[1], al[2], al[3], bh[nt * 2], bh[nt * 2 + 1]);
            }
        }

        {
            const int gr  = lane >> 2;
            const int gcq = (lane & 3) * 2;
            const int m = mi * 16 + gr;
#pragma unroll
            for (int nt = 0; nt < WNT; nt++) {
                const int gc = nh * (WNT * 8) + nt * 8 + gcq;
                *(float2*)&Gs[m * GSs + gc]       = make_float2(acc[nt][0], acc[nt][1]);
                *(float2*)&Gs[(m + 8) * GSs + gc] = make_float2(acc[nt][2], acc[nt][3]);
            }
        }
        __syncthreads();

#pragma unroll
        for (int i = tid; i < Bq * U; i += 256) {
            const int b = i >> USH, uu = i & (U - 1);
            const int u = u0 + uu;
            const size_t xb = ((size_t)b * T + tt) * Gq + u;
            const float iv = Gs[b * GSs + 0 * U + uu] + xpd[xb];
            const float fv = Gs[b * GSs + 1 * U + uu] + xpd[xb + 512];
            const float gv = Gs[b * GSs + 2 * U + uu] + xpd[xb + 1024];
            const float ov = Gs[b * GSs + 3 * U + uu] + xpd[xb + 1536];
            const float cOld = cD[b * Hq + u];
            const float si = 1.f / (1.f + expf(-iv));
            const float sf = 1.f / (1.f + expf(-fv));
            const float so = 1.f / (1.f + expf(-ov));
            const float cN = sf * cOld + si * tanhf(gv);
            const float hN = so * tanhf(cN);
            cD[b * Hq + u] = cN;
            hO[b * Hq + u] = hN;
            y[((size_t)b * T + tt) * yStride + dir * yDirMult + u] = hN;
        }

        gridBarrier();
        ping ^= 1;
    }

    if (hFin) {
        for (int i = tid; i < Bq * U; i += 256) {
            const int b = i >> USH, uu = i & (U - 1), u = u0 + uu;
            hFin[b * 1024 + dir * 512 + u] = hArr[ping][b * Hq + u];
            cFin[b * 1024 + dir * 512 + u] = cD[b * Hq + u];
        }
    }
}

#define SMEM_ENC (128 * 1024 + 2 * 32 * 1024 + 64 * 34 * 4)
#define SMEM_DEC (128 * 1024 + 2 * 16 * 1024 + 64 * 18 * 4)

// decoder input: concat(tgt_in, sc_emb[scenario[b]])
__global__ void build_dcat(const float* __restrict__ tgt, const float* __restrict__ scEmb,
                           const int* __restrict__ scen, float* __restrict__ out)
{
    const size_t i = (size_t)blockIdx.x * 256 + threadIdx.x;
    if (i >= (size_t)Bq * TDq * 640) return;
    const int r = (int)(i / 640);
    const int j = (int)(i - (size_t)r * 640);
    float v;
    if (j < 128) v = tgt[(size_t)r * 128 + j];
    else         v = scEmb[scen[r / TDq] * 512 + (j - 128)];
    out[i] = v;
}

// ---------------------------------------------------------------------------
extern "C" void kernel_launch(void* const* d_in, const int* in_sizes, int n_in,
                              void* d_out, int out_size)
{
    (void)in_sizes; (void)n_in; (void)out_size;
    const float* src   = (const float*)d_in[0];
    const float* tgt   = (const float*)d_in[1];
    const int*   scen  = (const int*)  d_in[2];
    const float* eWih0 = (const float*)d_in[3];
    const float* eWhh0 = (const float*)d_in[4];
    const float* eB0   = (const float*)d_in[5];
    const float* eWih  = (const float*)d_in[6];
    const float* eWhh  = (const float*)d_in[7];
    const float* eB    = (const float*)d_in[8];
    const float* hbW   = (const float*)d_in[9];
    const float* hbB   = (const float*)d_in[10];
    const float* cbW   = (const float*)d_in[11];
    const float* cbB   = (const float*)d_in[12];
    const float* scEmb = (const float*)d_in[13];
    const float* dWih0 = (const float*)d_in[14];
    const float* dWhh0 = (const float*)d_in[15];
    const float* dB0   = (const float*)d_in[16];
    const float* dWih  = (const float*)d_in[17];
    const float* dWhh  = (const float*)d_in[18];
    const float* dB    = (const float*)d_in[19];
    const float* outW  = (const float*)d_in[20];
    const float* outB  = (const float*)d_in[21];
    float* out = (float*)d_out;

    float *xp, *X0, *X1, *dcat, *hwork, *cst, *hsP, *csP, *h0P, *c0P;
    __nv_bfloat16 *Ah, *Al, *Wh, *Wl;
    cudaGetSymbolAddress((void**)&xp,    g_xp);
    cudaGetSymbolAddress((void**)&X0,    g_X0);
    cudaGetSymbolAddress((void**)&X1,    g_X1);
    cudaGetSymbolAddress((void**)&dcat,  g_dcat);
    cudaGetSymbolAddress((void**)&hwork, g_hwork);
    cudaGetSymbolAddress((void**)&cst,   g_cwork);
    cudaGetSymbolAddress((void**)&hsP,   g_hs);
    cudaGetSymbolAddress((void**)&csP,   g_cs);
    cudaGetSymbolAddress((void**)&h0P,   g_h0);
    cudaGetSymbolAddress((void**)&c0P,   g_c0);
    cudaGetSymbolAddress((void**)&Ah,    g_Ah);
    cudaGetSymbolAddress((void**)&Al,    g_Al);
    cudaGetSymbolAddress((void**)&Wh,    g_Wh);
    cudaGetSymbolAddress((void**)&Wl,    g_Wl);
    float* hA = hwork;
    float* hB = hwork + 2 * Bq * Hq;

    cudaFuncSetAttribute(lstm_persist<32>, cudaFuncAttributeMaxDynamicSharedMemorySize, SMEM_ENC);
    cudaFuncSetAttribute(lstm_persist<16>, cudaFuncAttributeMaxDynamicSharedMemorySize, SMEM_DEC);
    cudaFuncSetAttribute(mma_xp, cudaFuncAttributeMaxDynamicSharedMemorySize, MMA_SMEM_B);

    const int ME = Bq * TSq;   // 19200
    const int MD = Bq * TDq;   // 11520

    // ======================= encoder =======================
    const float* Xin = src;
    int inDim = Fq;
    float* Xcur = X0;
    for (int l = 0; l < Lq; l++) {
        const float* Wih = l ? eWih + (size_t)(l - 1) * 2 * Gq * 1024 : eWih0;
        const float* bih = l ? eB   + (size_t)(l - 1) * 2 * Gq        : eB0;

        const size_t nA = (size_t)ME * inDim;
        const size_t nW = (size_t)2 * Gq * inDim;
        conv_split<<<(int)((nA / 4 + 255) / 256), 256>>>(Xin, Ah, Al, nA);
        conv_split<<<(int)((nW / 4 + 255) / 256), 256>>>(Wih, Wh, Wl, nW);
        mma_xp<<<dim3(Gq / 128, ME / 128, 2), 256, MMA_SMEM_B>>>(
            Ah, Al, Wh, Wl, bih, xp, ME, Gq, inDim,
            (size_t)Gq * inDim, (size_t)Gq, (size_t)ME * Gq, 0);

        const float* Whh = l ? eWhh + (size_t)(l - 1) * 2 * Gq * Hq : eWhh0;
        lstm_persist<32><<<128, 256, SMEM_ENC>>>(
            xp, Whh, nullptr, nullptr, hA, hB, cst, Xcur,
            hsP + (size_t)l * Bq * 1024, csP + (size_t)l * Bq * 1024,
            TSq, 1, 1024, 512);

        Xin = Xcur; inDim = 1024;
        Xcur = (Xcur == X0) ? X1 : X0;
    }

    // ======================= bridges (tanh, tensor cores) =======================
    conv_split<<<(int)(((size_t)Lq * Bq * 1024 / 4 + 255) / 256), 256>>>(hsP, Ah, Al, (size_t)Lq * Bq * 1024);
    conv_split<<<(int)(((size_t)Hq * 1024 / 4 + 255) / 256), 256>>>(hbW, Wh, Wl, (size_t)Hq * 1024);
    mma_xp<<<dim3(Hq / 128, (Lq * Bq) / 128, 1), 256, MMA_SMEM_B>>>(
        Ah, Al, Wh, Wl, hbB, h0P, Lq * Bq, Hq, 1024, 0, 0, 0, 1);
    conv_split<<<(int)(((size_t)Lq * Bq * 1024 / 4 + 255) / 256), 256>>>(csP, Ah, Al, (size_t)Lq * Bq * 1024);
    conv_split<<<(int)(((size_t)Hq * 1024 / 4 + 255) / 256), 256>>>(cbW, Wh, Wl, (size_t)Hq * 1024);
    mma_xp<<<dim3(Hq / 128, (Lq * Bq) / 128, 1), 256, MMA_SMEM_B>>>(
        Ah, Al, Wh, Wl, cbB, c0P, Lq * Bq, Hq, 1024, 0, 0, 0, 1);

    // ======================= decoder =======================
    build_dcat<<<(int)(((size_t)Bq * TDq * 640 + 255) / 256), 256>>>(tgt, scEmb, scen, dcat);

    Xin = dcat; inDim = Fq + Hq;
    for (int l = 0; l < Lq; l++) {
        const float* Wih = l ? dWih + (size_t)(l - 1) * Gq * Hq : dWih0;
        const float* bih = l ? dB   + (size_t)(l - 1) * Gq      : dB0;

        const size_t nA = (size_t)MD * inDim;
        const size_t nW = (size_t)Gq * inDim;
        conv_split<<<(int)((nA / 4 + 255) / 256), 256>>>(Xin, Ah, Al, nA);
        conv_split<<<(int)((nW / 4 + 255) / 256), 256>>>(Wih, Wh, Wl, nW);
        mma_xp<<<dim3(Gq / 128, MD / 128, 1), 256, MMA_SMEM_B>>>(
            Ah, Al, Wh, Wl, bih, xp, MD, Gq, inDim, 0, 0, 0, 0);

        const float* Whh = l ? dWhh + (size_t)(l - 1) * Gq * Hq : dWhh0;
        lstm_persist<16><<<128, 256, SMEM_DEC>>>(
            xp, Whh, h0P + (size_t)l * Bq * Hq, c0P + (size_t)l * Bq * Hq,
            hA, hB, cst, Xcur, nullptr, nullptr,
            TDq, 0, 512, 0);

        Xin = Xcur; inDim = Hq;
        Xcur = (Xcur == X0) ? X1 : X0;
    }

    // output projection (tensor cores) straight into d_out
    conv_split<<<(int)(((size_t)MD * Hq / 4 + 255) / 256), 256>>>(Xin, Ah, Al, (size_t)MD * Hq);
    conv_split<<<(int)(((size_t)Fq * Hq / 4 + 255) / 256), 256>>>(outW, Wh, Wl, (size_t)Fq * Hq);
    mma_xp<<<dim3(Fq / 128, MD / 128, 1), 256, MMA_SMEM_B>>>(
        Ah, Al, Wh, Wl, outB, out, MD, Fq, Hq, 0, 0, 0, 0);
}

// round 8
// speedup vs baseline: 1.1115x; 1.1115x over previous
#include <cuda_runtime.h>
#include <cuda_bf16.h>
#include <math.h>
#include <stdint.h>

#define Bq 64
#define TSq 300
#define TDq 180
#define Fq 128
#define Hq 512
#define Lq 4
#define Gq 2048   // 4*H

// ---------------- static device scratch (no runtime allocation) ----------------
__device__ float g_xp[(size_t)2 * Bq * TSq * Gq];
__device__ float g_X0[(size_t)Bq * TSq * 1024];
__device__ float g_X1[(size_t)Bq * TSq * 1024];
__device__ float g_dcat[(size_t)Bq * TDq * 640];
__device__ unsigned g_hwork[2][2 * Bq * Hq];          // packed bf16 hi|lo h state
__device__ float g_cwork[2 * Bq * Hq];
__device__ float g_hs[Lq * Bq * 1024];
__device__ float g_cs[Lq * Bq * 1024];
__device__ float g_h0[Lq * Bq * Hq];
__device__ float g_c0[Lq * Bq * Hq];
__device__ unsigned g_barCnt;
__device__ unsigned g_barGen;
// bf16 split buffers for tensor-core GEMMs
__device__ __nv_bfloat16 g_Ah[(size_t)Bq * TSq * 1024];
__device__ __nv_bfloat16 g_Al[(size_t)Bq * TSq * 1024];
__device__ __nv_bfloat16 g_Wh[(size_t)2 * Gq * 1024];
__device__ __nv_bfloat16 g_Wl[(size_t)2 * Gq * 1024];

// -------- mma.sync / ldmatrix / cp.async helpers (compute_103-safe) -----
__device__ __forceinline__ uint32_t smem_u32(const void* p) {
    uint32_t a;
    asm("{ .reg .u64 t; cvta.to.shared.u64 t, %1; cvt.u32.u64 %0, t; }" : "=r"(a) : "l"(p));
    return a;
}
#define LDM_X4(r0, r1, r2, r3, addr) \
    asm volatile("ldmatrix.sync.aligned.m8n8.x4.shared.b16 {%0,%1,%2,%3}, [%4];" \
        : "=r"(r0), "=r"(r1), "=r"(r2), "=r"(r3) : "r"(addr))
#define LDM_X2(r0, r1, addr) \
    asm volatile("ldmatrix.sync.aligned.m8n8.x2.shared.b16 {%0,%1}, [%2];" \
        : "=r"(r0), "=r"(r1) : "r"(addr))
#define MMA_BF16(c0, c1, c2, c3, a0, a1, a2, a3, b0, b1) \
    asm volatile("mma.sync.aligned.m16n8k16.row.col.f32.bf16.bf16.f32 " \
        "{%0,%1,%2,%3}, {%4,%5,%6,%7}, {%8,%9}, {%0,%1,%2,%3};" \
        : "+f"(c0), "+f"(c1), "+f"(c2), "+f"(c3) \
        : "r"(a0), "r"(a1), "r"(a2), "r"(a3), "r"(b0), "r"(b1))
#define CPA16(dst, src) \
    asm volatile("cp.async.cg.shared.global [%0], [%1], 16;" :: "r"(dst), "l"(src))
#define CPA_COMMIT() asm volatile("cp.async.commit_group;" ::: "memory")
#define CPA_WAIT(n)  asm volatile("cp.async.wait_group %0;" :: "n"(n) : "memory")

__device__ __forceinline__ uint32_t bf2pack(float fhi, float flo) {
    uint32_t r;
    asm("cvt.rn.bf16x2.f32 %0, %1, %2;" : "=r"(r) : "f"(fhi), "f"(flo));
    return r;
}
__device__ __forceinline__ float trunc_hi(float f) {
    return __uint_as_float(__float_as_uint(f) & 0xFFFF0000u);
}
// pack fp32 -> u32: [hi bf16 (trunc) | lo bf16 (RN residual)]
__device__ __forceinline__ unsigned packHL(float f) {
    const float lo = f - trunc_hi(f);
    unsigned lo16;
    asm("{ .reg .b16 t; cvt.rn.bf16.f32 t, %1; cvt.u32.u16 %0, t; }" : "=r"(lo16) : "f"(lo));
    return (__float_as_uint(f) & 0xFFFF0000u) | lo16;
}
__device__ __forceinline__ float unpackHL(unsigned w) {
    return __uint_as_float(w & 0xFFFF0000u) + __uint_as_float(w << 16);
}

// ---------------------------------------------------------------------------
// software grid barrier (single counter; gridDim.x == 128, co-resident)
// ---------------------------------------------------------------------------
__device__ __forceinline__ void gridBarrier()
{
    __syncthreads();
    if (threadIdx.x == 0) {
        const unsigned gen = *((volatile unsigned*)&g_barGen);
        __threadfence();
        if (atomicAdd(&g_barCnt, 1u) == gridDim.x - 1u) {
            atomicExch(&g_barCnt, 0u);
            __threadfence();
            atomicAdd(&g_barGen, 1u);
        } else {
            while (*((volatile unsigned*)&g_barGen) == gen) { __nanosleep(64); }
        }
        __threadfence();
    }
    __syncthreads();
}

// ---------------------------------------------------------------------------
// fp32 -> bf16 hi/lo split (elementwise), n % 4 == 0
// ---------------------------------------------------------------------------
__global__ void conv_split(const float* __restrict__ in, __nv_bfloat16* __restrict__ hi,
                           __nv_bfloat16* __restrict__ lo, size_t n)
{
    const size_t i = ((size_t)blockIdx.x * 256 + threadIdx.x) * 4;
    if (i >= n) return;
    const float4 v = *(const float4*)(in + i);
    __nv_bfloat16 h0 = __float2bfloat16(v.x), h1 = __float2bfloat16(v.y);
    __nv_bfloat16 h2 = __float2bfloat16(v.z), h3 = __float2bfloat16(v.w);
    __nv_bfloat16 l0 = __float2bfloat16(v.x - __bfloat162float(h0));
    __nv_bfloat16 l1 = __float2bfloat16(v.y - __bfloat162float(h1));
    __nv_bfloat16 l2 = __float2bfloat16(v.z - __bfloat162float(h2));
    __nv_bfloat16 l3 = __float2bfloat16(v.w - __bfloat162float(h3));
    __nv_bfloat162 hp0(h0, h1), hp1(h2, h3), lp0(l0, l1), lp1(l2, l3);
    *(uint2*)(hi + i) = make_uint2(*(uint32_t*)&hp0, *(uint32_t*)&hp1);
    *(uint2*)(lo + i) = make_uint2(*(uint32_t*)&lp0, *(uint32_t*)&lp1);
}

// ---------------------------------------------------------------------------
// Split-bf16 tensor-core GEMM: C[M,N] = op(A[M,K] @ W[N,K]^T + b)
// D = Ah*Wh + Ah*Wl + Al*Wh. CTA tile 128x128, 512 threads (16 warps 4x4),
// warp tile 32x32. K chunks of 64, 2-stage cp.async, 128B smem rows with
// conflict-free g^=(row&7) swizzle. M%128==0, N%128==0, K%64==0.
// ---------------------------------------------------------------------------
#define XT_TILE_B   16384                    // one 128x64 bf16 tile
#define XT_STAGE_B  (4 * XT_TILE_B)          // Ah|Al|Wh|Wl = 64KB
#define XT_SMEM_B   (2 * XT_STAGE_B)         // 128KB

__global__ __launch_bounds__(512, 1)
void mma_xp(const __nv_bfloat16* __restrict__ Ah, const __nv_bfloat16* __restrict__ Al,
            const __nv_bfloat16* __restrict__ Wh, const __nv_bfloat16* __restrict__ Wl,
            const float* __restrict__ bias, float* __restrict__ C,
            int M, int N, int K, size_t wZ, size_t bZ, size_t cZ, int act)
{
    extern __shared__ __align__(128) char smem[];
    const uint32_t sbase = smem_u32(smem);

    Wh   += blockIdx.z * wZ;
    Wl   += blockIdx.z * wZ;
    bias += blockIdx.z * bZ;
    C    += blockIdx.z * cZ;
    const int n0 = blockIdx.x * 128;
    const int m0 = blockIdx.y * 128;

    const int tid  = threadIdx.x;
    const int lane = tid & 31;
    const int warp = tid >> 5;
    const int wm = warp >> 2;          // 0..3 : 32-row block
    const int wn = warp & 3;           // 0..3 : 32-col block

    float acc[2][4][4];
#pragma unroll
    for (int i = 0; i < 2; i++)
#pragma unroll
        for (int j = 0; j < 4; j++)
#pragma unroll
            for (int q = 0; q < 4; q++) acc[i][j][q] = 0.f;

    // cp.async granule mapping: 1024 granules per tile, 2 per thread
    const int r0 = tid >> 3,           gg0 = tid & 7;
    const int r1 = (tid + 512) >> 3,   gg1 = (tid + 512) & 7;
    const uint32_t so0 = (uint32_t)(r0 * 128 + ((gg0 ^ (r0 & 7)) << 4));
    const uint32_t so1 = (uint32_t)(r1 * 128 + ((gg1 ^ (r1 & 7)) << 4));

    // ldmatrix address components
    const int arowb = wm * 32 + (lane & 15);   // + mt*16
    const int agoff = lane >> 4;
    const int brow  = wn * 32 + (lane & 7);    // + (p*2+bnt)*8
    const int bgoff = (lane >> 3) & 1;
    const int bnt   = lane >> 4;

    const int nch = K >> 6;

#define XISSUE(c) do { \
    const uint32_t _buf = sbase + (uint32_t)((c) & 1) * XT_STAGE_B; \
    const size_t _k0 = (size_t)((c) << 6); \
    CPA16(_buf + 0 * XT_TILE_B + so0, Ah + (size_t)(m0 + r0) * K + _k0 + gg0 * 8); \
    CPA16(_buf + 1 * XT_TILE_B + so0, Al + (size_t)(m0 + r0) * K + _k0 + gg0 * 8); \
    CPA16(_buf + 2 * XT_TILE_B + so0, Wh + (size_t)(n0 + r0) * K + _k0 + gg0 * 8); \
    CPA16(_buf + 3 * XT_TILE_B + so0, Wl + (size_t)(n0 + r0) * K + _k0 + gg0 * 8); \
    CPA16(_buf + 0 * XT_TILE_B + so1, Ah + (size_t)(m0 + r1) * K + _k0 + gg1 * 8); \
    CPA16(_buf + 1 * XT_TILE_B + so1, Al + (size_t)(m0 + r1) * K + _k0 + gg1 * 8); \
    CPA16(_buf + 2 * XT_TILE_B + so1, Wh + (size_t)(n0 + r1) * K + _k0 + gg1 * 8); \
    CPA16(_buf + 3 * XT_TILE_B + so1, Wl + (size_t)(n0 + r1) * K + _k0 + gg1 * 8); \
} while (0)

    XISSUE(0); CPA_COMMIT();

    for (int c = 0; c < nch; c++) {
        if (c + 1 < nch) { XISSUE(c + 1); CPA_COMMIT(); CPA_WAIT(1); }
        else             { CPA_WAIT(0); }
        __syncthreads();

        const uint32_t buf = sbase + (uint32_t)(c & 1) * XT_STAGE_B;
        const uint32_t aH = buf + 0 * XT_TILE_B;
        const uint32_t aL = buf + 1 * XT_TILE_B;
        const uint32_t wH = buf + 2 * XT_TILE_B;
        const uint32_t wL = buf + 3 * XT_TILE_B;

#pragma unroll
        for (int ks = 0; ks < 4; ks++) {
            uint32_t afh[2][4], afl[2][4], bh[4][2], bl[4][2];
#pragma unroll
            for (int mt = 0; mt < 2; mt++) {
                const int rA = arowb + mt * 16;
                const uint32_t off = (uint32_t)(rA * 128 + (((ks * 2 + agoff) ^ (rA & 7)) << 4));
                LDM_X4(afh[mt][0], afh[mt][1], afh[mt][2], afh[mt][3], aH + off);
                LDM_X4(afl[mt][0], afl[mt][1], afl[mt][2], afl[mt][3], aL + off);
            }
#pragma unroll
            for (int p = 0; p < 2; p++) {
                const int rB = brow + (p * 2 + bnt) * 8;
                const uint32_t off = (uint32_t)(rB * 128 + (((ks * 2 + bgoff) ^ (rB & 7)) << 4));
                LDM_X4(bh[p * 2][0], bh[p * 2][1], bh[p * 2 + 1][0], bh[p * 2 + 1][1], wH + off);
                LDM_X4(bl[p * 2][0], bl[p * 2][1], bl[p * 2 + 1][0], bl[p * 2 + 1][1], wL + off);
            }
            // term sweeps: Ah*Wh, Ah*Wl, Al*Wh (no same-acc adjacency)
#pragma unroll
            for (int mt = 0; mt < 2; mt++)
#pragma unroll
                for (int nt = 0; nt < 4; nt++)
                    MMA_BF16(acc[mt][nt][0], acc[mt][nt][1], acc[mt][nt][2], acc[mt][nt][3],
                             afh[mt][0], afh[mt][1], afh[mt][2], afh[mt][3],
                             bh[nt][0], bh[nt][1]);
#pragma unroll
            for (int mt = 0; mt < 2; mt++)
#pragma unroll
                for (int nt = 0; nt < 4; nt++)
                    MMA_BF16(acc[mt][nt][0], acc[mt][nt][1], acc[mt][nt][2], acc[mt][nt][3],
                             afh[mt][0], afh[mt][1], afh[mt][2], afh[mt][3],
                             bl[nt][0], bl[nt][1]);
#pragma unroll
            for (int mt = 0; mt < 2; mt++)
#pragma unroll
                for (int nt = 0; nt < 4; nt++)
                    MMA_BF16(acc[mt][nt][0], acc[mt][nt][1], acc[mt][nt][2], acc[mt][nt][3],
                             afl[mt][0], afl[mt][1], afl[mt][2], afl[mt][3],
                             bh[nt][0], bh[nt][1]);
        }
        __syncthreads();
    }

    const int mE = m0 + wm * 32 + (lane >> 2);
    const int nE = n0 + wn * 32 + (lane & 3) * 2;
#pragma unroll
    for (int mt = 0; mt < 2; mt++) {
#pragma unroll
        for (int nt = 0; nt < 4; nt++) {
            const int m = mE + mt * 16;
            const int n = nE + nt * 8;
            const float b0 = bias[n], b1 = bias[n + 1];
            float v00 = acc[mt][nt][0] + b0, v01 = acc[mt][nt][1] + b1;
            float v10 = acc[mt][nt][2] + b0, v11 = acc[mt][nt][3] + b1;
            if (act) { v00 = tanhf(v00); v01 = tanhf(v01); v10 = tanhf(v10); v11 = tanhf(v11); }
            *(float2*)(C + (size_t)m * N + n)       = make_float2(v00, v01);
            *(float2*)(C + (size_t)(m + 8) * N + n) = make_float2(v10, v11);
        }
    }
}

// ---------------------------------------------------------------------------
// Persistent LSTM layer with tensor-core recurrence.
// h state in global as packed u32 (bf16 hi|lo) -> staging is PRMT-only.
// NBL=32: encoder (2 dirs x 64 blocks); NBL=16: decoder (128 blocks).
// ---------------------------------------------------------------------------
template<int NBL>
__global__ __launch_bounds__(256)
void lstm_persist(const float* __restrict__ xp, const float* __restrict__ Whh,
                  const float* __restrict__ h0, const float* __restrict__ c0,
                  unsigned* __restrict__ hA, unsigned* __restrict__ hB,
                  float* __restrict__ cSt, float* __restrict__ y,
                  float* __restrict__ hFin, float* __restrict__ cFin,
                  int T, int revDir1, int yStride, int yDirMult)
{
    constexpr int U    = NBL / 4;
    constexpr int USH  = (NBL == 32) ? 3 : 2;
    constexpr int WNT  = NBL / 16;
    constexpr int GSs  = NBL + 2;
    constexpr uint32_t S_AH = 0;
    constexpr uint32_t S_AL = 64 * 1024;
    constexpr uint32_t S_BH = 128 * 1024;
    constexpr uint32_t S_BL = S_BH + NBL * 1024;
    constexpr uint32_t S_GS = S_BL + NBL * 1024;

    extern __shared__ __align__(128) char smem[];
    const uint32_t sb = smem_u32(smem);
    float* Gs = (float*)(smem + S_GS);

    const int tid  = threadIdx.x;
    const int lane = tid & 31;
    const int warp = tid >> 5;
    const int mi = warp >> 1;
    const int nh = warp & 1;

    int dir, u0;
    if (NBL == 32) { dir = blockIdx.x >> 6; u0 = (blockIdx.x & 63) * 8; }
    else           { dir = 0;               u0 = blockIdx.x * 4; }

    const float* xpd = xp  + (size_t)dir * Bq * T * Gq;
    const float* Wd  = Whh + (size_t)dir * Gq * Hq;
    unsigned* hArr[2] = { hA + dir * Bq * Hq, hB + dir * Bq * Hq };
    float* cD = cSt + dir * Bq * Hq;

    // ---- convert Whh rows into smem bf16 hi/lo, swizzled (once) ----
    for (int i = tid; i < NBL * 64; i += 256) {
        const int row = i >> 6;
        const int g   = i & 63;
        const int gate = row / U;
        const int uu   = row & (U - 1);
        const int wrow = (gate << 9) + u0 + uu;
        const float4 va = *(const float4*)(Wd + (size_t)wrow * Hq + g * 8);
        const float4 vb = *(const float4*)(Wd + (size_t)wrow * Hq + g * 8 + 4);
        uint4 hi, lo;
        hi.x = __byte_perm(__float_as_uint(va.x), __float_as_uint(va.y), 0x7632);
        hi.y = __byte_perm(__float_as_uint(va.z), __float_as_uint(va.w), 0x7632);
        hi.z = __byte_perm(__float_as_uint(vb.x), __float_as_uint(vb.y), 0x7632);
        hi.w = __byte_perm(__float_as_uint(vb.z), __float_as_uint(vb.w), 0x7632);
        lo.x = bf2pack(va.y - trunc_hi(va.y), va.x - trunc_hi(va.x));
        lo.y = bf2pack(va.w - trunc_hi(va.w), va.z - trunc_hi(va.z));
        lo.z = bf2pack(vb.y - trunc_hi(vb.y), vb.x - trunc_hi(vb.x));
        lo.w = bf2pack(vb.w - trunc_hi(vb.w), vb.z - trunc_hi(vb.z));
        const uint32_t so = (uint32_t)(row * 1024 + ((g ^ (row & 7)) << 4));
        *(uint4*)(smem + S_BH + so) = hi;
        *(uint4*)(smem + S_BL + so) = lo;
    }

    // ---- init h (packed), c ----
    for (int i = tid; i < Bq * U; i += 256) {
        const int b = i >> USH, uu = i & (U - 1), u = u0 + uu;
        hArr[0][b * Hq + u] = h0 ? packHL(h0[b * Hq + u]) : 0u;
        cD        [b * Hq + u] = c0 ? c0[b * Hq + u] : 0.f;
    }
    gridBarrier();

    const int rowA = (lane & 15);
    const int agoff = lane >> 4;
    const int bnt   = lane >> 4;
    const int bgoff = (lane >> 3) & 1;

    int ping = 0;
    for (int t = 0; t < T; t++) {
        const int tt = (dir == 1 && revDir1) ? (T - 1 - t) : t;
        const unsigned* hI = hArr[ping];
        unsigned*       hO = hArr[ping ^ 1];

        // ---- stage packed h -> smem hi/lo granules (PRMT only) ----
#pragma unroll
        for (int it = 0; it < 16; it++) {
            const int slot = tid + it * 256;
            const int row = slot >> 6, g = slot & 63;
            const uint4* p = (const uint4*)(hI + (size_t)row * Hq + g * 8);
            const uint4 v0 = __ldcg(p);
            const uint4 v1 = __ldcg(p + 1);
            uint4 hi, lo;
            hi.x = __byte_perm(v0.x, v0.y, 0x7632); hi.y = __byte_perm(v0.z, v0.w, 0x7632);
            hi.z = __byte_perm(v1.x, v1.y, 0x7632); hi.w = __byte_perm(v1.z, v1.w, 0x7632);
            lo.x = __byte_perm(v0.x, v0.y, 0x5410); lo.y = __byte_perm(v0.z, v0.w, 0x5410);
            lo.z = __byte_perm(v1.x, v1.y, 0x5410); lo.w = __byte_perm(v1.z, v1.w, 0x5410);
            const uint32_t so = (uint32_t)(row * 1024 + ((g ^ (row & 7)) << 4));
            *(uint4*)(smem + S_AH + so) = hi;
            *(uint4*)(smem + S_AL + so) = lo;
        }
        __syncthreads();

        float acc[WNT][4];
#pragma unroll
        for (int nt = 0; nt < WNT; nt++)
#pragma unroll
            for (int q = 0; q < 4; q++) acc[nt][q] = 0.f;

#pragma unroll 4
        for (int ks = 0; ks < 32; ks++) {
            const int rA = mi * 16 + rowA;
            const uint32_t aoff = (uint32_t)(rA * 1024 + (((ks * 2 + agoff) ^ (rA & 7)) << 4));
            uint32_t ah[4], al[4], bh[2 * WNT], bl[2 * WNT];
            LDM_X4(ah[0], ah[1], ah[2], ah[3], sb + S_AH + aoff);
            LDM_X4(al[0], al[1], al[2], al[3], sb + S_AL + aoff);
            if (WNT == 2) {
                const int rB = nh * 16 + bnt * 8 + (lane & 7);
                const uint32_t boff = (uint32_t)(rB * 1024 + (((ks * 2 + bgoff) ^ (rB & 7)) << 4));
                LDM_X4(bh[0], bh[1], bh[2], bh[3], sb + S_BH + boff);
                LDM_X4(bl[0], bl[1], bl[2], bl[3], sb + S_BL + boff);
            } else {
                const int rB = nh * 8 + (lane & 7);
                const uint32_t boff = (uint32_t)(rB * 1024 + (((ks * 2 + bgoff) ^ (rB & 7)) << 4));
                LDM_X2(bh[0], bh[1], sb + S_BH + boff);
                LDM_X2(bl[0], bl[1], sb + S_BL + boff);
            }
            // term sweeps (no same-acc adjacency within a term)
#pragma unroll
            for (int nt = 0; nt < WNT; nt++)
                MMA_BF16(acc[nt][0], acc[nt][1], acc[nt][2], acc[nt][3],
                         ah[0], ah[1], ah[2], ah[3], bh[nt * 2], bh[nt * 2 + 1]);
#pragma unroll
            for (int nt = 0; nt < WNT; nt++)
                MMA_BF16(acc[nt][0], acc[nt][1], acc[nt][2], acc[nt][3],
                         ah[0], ah[1], ah[2], ah[3], bl[nt * 2], bl[nt * 2 + 1]);
#pragma unroll
            for (int nt = 0; nt < WNT; nt++)
                MMA_BF16(acc[nt][0], acc[nt][1], acc[nt][2], acc[nt][3],
                         al[0], al[1], al[2], al[3], bh[nt * 2], bh[nt * 2 + 1]);
        }

        {
            const int gr  = lane >> 2;
            const int gcq = (lane & 3) * 2;
            const int m = mi * 16 + gr;
#pragma unroll
            for (int nt = 0; nt < WNT; nt++) {
                const int gc = nh * (WNT * 8) + nt * 8 + gcq;
                *(float2*)&Gs[m * GSs + gc]       = make_float2(acc[nt][0], acc[nt][1]);
                *(float2*)&Gs[(m + 8) * GSs + gc] = make_float2(acc[nt][2], acc[nt][3]);
            }
        }
        __syncthreads();

#pragma unroll
        for (int i = tid; i < Bq * U; i += 256) {
            const int b = i >> USH, uu = i & (U - 1);
            const int u = u0 + uu;
            const size_t xb = ((size_t)b * T + tt) * Gq + u;
            const float iv = Gs[b * GSs + 0 * U + uu] + xpd[xb];
            const float fv = Gs[b * GSs + 1 * U + uu] + xpd[xb + 512];
            const float gv = Gs[b * GSs + 2 * U + uu] + xpd[xb + 1024];
            const float ov = Gs[b * GSs + 3 * U + uu] + xpd[xb + 1536];
            const float cOld = cD[b * Hq + u];
            const float si = 1.f / (1.f + expf(-iv));
            const float sf = 1.f / (1.f + expf(-fv));
            const float so = 1.f / (1.f + expf(-ov));
            const float cN = sf * cOld + si * tanhf(gv);
            const float hN = so * tanhf(cN);
            cD[b * Hq + u] = cN;
            hO[b * Hq + u] = packHL(hN);
            y[((size_t)b * T + tt) * yStride + dir * yDirMult + u] = hN;
        }

        gridBarrier();
        ping ^= 1;
    }

    if (hFin) {
        for (int i = tid; i < Bq * U; i += 256) {
            const int b = i >> USH, uu = i & (U - 1), u = u0 + uu;
            hFin[b * 1024 + dir * 512 + u] = unpackHL(hArr[ping][b * Hq + u]);
            cFin[b * 1024 + dir * 512 + u] = cD[b * Hq + u];
        }
    }
}

#define SMEM_ENC (128 * 1024 + 2 * 32 * 1024 + 64 * 34 * 4)
#define SMEM_DEC (128 * 1024 + 2 * 16 * 1024 + 64 * 18 * 4)

// decoder input: concat(tgt_in, sc_emb[scenario[b]])
__global__ void build_dcat(const float* __restrict__ tgt, const float* __restrict__ scEmb,
                           const int* __restrict__ scen, float* __restrict__ out)
{
    const size_t i = (size_t)blockIdx.x * 256 + threadIdx.x;
    if (i >= (size_t)Bq * TDq * 640) return;
    const int r = (int)(i / 640);
    const int j = (int)(i - (size_t)r * 640);
    float v;
    if (j < 128) v = tgt[(size_t)r * 128 + j];
    else         v = scEmb[scen[r / TDq] * 512 + (j - 128)];
    out[i] = v;
}

// ---------------------------------------------------------------------------
extern "C" void kernel_launch(void* const* d_in, const int* in_sizes, int n_in,
                              void* d_out, int out_size)
{
    (void)in_sizes; (void)n_in; (void)out_size;
    const float* src   = (const float*)d_in[0];
    const float* tgt   = (const float*)d_in[1];
    const int*   scen  = (const int*)  d_in[2];
    const float* eWih0 = (const float*)d_in[3];
    const float* eWhh0 = (const float*)d_in[4];
    const float* eB0   = (const float*)d_in[5];
    const float* eWih  = (const float*)d_in[6];
    const float* eWhh  = (const float*)d_in[7];
    const float* eB    = (const float*)d_in[8];
    const float* hbW   = (const float*)d_in[9];
    const float* hbB   = (const float*)d_in[10];
    const float* cbW   = (const float*)d_in[11];
    const float* cbB   = (const float*)d_in[12];
    const float* scEmb = (const float*)d_in[13];
    const float* dWih0 = (const float*)d_in[14];
    const float* dWhh0 = (const float*)d_in[15];
    const float* dB0   = (const float*)d_in[16];
    const float* dWih  = (const float*)d_in[17];
    const float* dWhh  = (const float*)d_in[18];
    const float* dB    = (const float*)d_in[19];
    const float* outW  = (const float*)d_in[20];
    const float* outB  = (const float*)d_in[21];
    float* out = (float*)d_out;

    float *xp, *X0, *X1, *dcat, *cst, *hsP, *csP, *h0P, *c0P;
    unsigned* hwork;
    __nv_bfloat16 *Ah, *Al, *Wh, *Wl;
    cudaGetSymbolAddress((void**)&xp,    g_xp);
    cudaGetSymbolAddress((void**)&X0,    g_X0);
    cudaGetSymbolAddress((void**)&X1,    g_X1);
    cudaGetSymbolAddress((void**)&dcat,  g_dcat);
    cudaGetSymbolAddress((void**)&hwork, g_hwork);
    cudaGetSymbolAddress((void**)&cst,   g_cwork);
    cudaGetSymbolAddress((void**)&hsP,   g_hs);
    cudaGetSymbolAddress((void**)&csP,   g_cs);
    cudaGetSymbolAddress((void**)&h0P,   g_h0);
    cudaGetSymbolAddress((void**)&c0P,   g_c0);
    cudaGetSymbolAddress((void**)&Ah,    g_Ah);
    cudaGetSymbolAddress((void**)&Al,    g_Al);
    cudaGetSymbolAddress((void**)&Wh,    g_Wh);
    cudaGetSymbolAddress((void**)&Wl,    g_Wl);
    unsigned* hA = hwork;
    unsigned* hB = hwork + 2 * Bq * Hq;

    cudaFuncSetAttribute(lstm_persist<32>, cudaFuncAttributeMaxDynamicSharedMemorySize, SMEM_ENC);
    cudaFuncSetAttribute(lstm_persist<16>, cudaFuncAttributeMaxDynamicSharedMemorySize, SMEM_DEC);
    cudaFuncSetAttribute(mma_xp, cudaFuncAttributeMaxDynamicSharedMemorySize, XT_SMEM_B);

    const int ME = Bq * TSq;   // 19200
    const int MD = Bq * TDq;   // 11520

    // ======================= encoder =======================
    const float* Xin = src;
    int inDim = Fq;
    float* Xcur = X0;
    for (int l = 0; l < Lq; l++) {
        const float* Wih = l ? eWih + (size_t)(l - 1) * 2 * Gq * 1024 : eWih0;
        const float* bih = l ? eB   + (size_t)(l - 1) * 2 * Gq        : eB0;

        const size_t nA = (size_t)ME * inDim;
        const size_t nW = (size_t)2 * Gq * inDim;
        conv_split<<<(int)((nA / 4 + 255) / 256), 256>>>(Xin, Ah, Al, nA);
        conv_split<<<(int)((nW / 4 + 255) / 256), 256>>>(Wih, Wh, Wl, nW);
        mma_xp<<<dim3(Gq / 128, ME / 128, 2), 512, XT_SMEM_B>>>(
            Ah, Al, Wh, Wl, bih, xp, ME, Gq, inDim,
            (size_t)Gq * inDim, (size_t)Gq, (size_t)ME * Gq, 0);

        const float* Whh = l ? eWhh + (size_t)(l - 1) * 2 * Gq * Hq : eWhh0;
        lstm_persist<32><<<128, 256, SMEM_ENC>>>(
            xp, Whh, nullptr, nullptr, hA, hB, cst, Xcur,
            hsP + (size_t)l * Bq * 1024, csP + (size_t)l * Bq * 1024,
            TSq, 1, 1024, 512);

        Xin = Xcur; inDim = 1024;
        Xcur = (Xcur == X0) ? X1 : X0;
    }

    // ======================= bridges (tanh, tensor cores) =======================
    conv_split<<<(int)(((size_t)Lq * Bq * 1024 / 4 + 255) / 256), 256>>>(hsP, Ah, Al, (size_t)Lq * Bq * 1024);
    conv_split<<<(int)(((size_t)Hq * 1024 / 4 + 255) / 256), 256>>>(hbW, Wh, Wl, (size_t)Hq * 1024);
    mma_xp<<<dim3(Hq / 128, (Lq * Bq) / 128, 1), 512, XT_SMEM_B>>>(
        Ah, Al, Wh, Wl, hbB, h0P, Lq * Bq, Hq, 1024, 0, 0, 0, 1);
    conv_split<<<(int)(((size_t)Lq * Bq * 1024 / 4 + 255) / 256), 256>>>(csP, Ah, Al, (size_t)Lq * Bq * 1024);
    conv_split<<<(int)(((size_t)Hq * 1024 / 4 + 255) / 256), 256>>>(cbW, Wh, Wl, (size_t)Hq * 1024);
    mma_xp<<<dim3(Hq / 128, (Lq * Bq) / 128, 1), 512, XT_SMEM_B>>>(
        Ah, Al, Wh, Wl, cbB, c0P, Lq * Bq, Hq, 1024, 0, 0, 0, 1);

    // ======================= decoder =======================
    build_dcat<<<(int)(((size_t)Bq * TDq * 640 + 255) / 256), 256>>>(tgt, scEmb, scen, dcat);

    Xin = dcat; inDim = Fq + Hq;
    for (int l = 0; l < Lq; l++) {
        const float* Wih = l ? dWih + (size_t)(l - 1) * Gq * Hq : dWih0;
        const float* bih = l ? dB   + (size_t)(l - 1) * Gq      : dB0;

        const size_t nA = (size_t)MD * inDim;
        const size_t nW = (size_t)Gq * inDim;
        conv_split<<<(int)((nA / 4 + 255) / 256), 256>>>(Xin, Ah, Al, nA);
        conv_split<<<(int)((nW / 4 + 255) / 256), 256>>>(Wih, Wh, Wl, nW);
        mma_xp<<<dim3(Gq / 128, MD / 128, 1), 512, XT_SMEM_B>>>(
            Ah, Al, Wh, Wl, bih, xp, MD, Gq, inDim, 0, 0, 0, 0);

        const float* Whh = l ? dWhh + (size_t)(l - 1) * Gq * Hq : dWhh0;
        lstm_persist<16><<<128, 256, SMEM_DEC>>>(
            xp, Whh, h0P + (size_t)l * Bq * Hq, c0P + (size_t)l * Bq * Hq,
            hA, hB, cst, Xcur, nullptr, nullptr,
            TDq, 0, 512, 0);

        Xin = Xcur; inDim = Hq;
        Xcur = (Xcur == X0) ? X1 : X0;
    }

    // output projection (tensor cores) straight into d_out
    conv_split<<<(int)(((size_t)MD * Hq / 4 + 255) / 256), 256>>>(Xin, Ah, Al, (size_t)MD * Hq);
    conv_split<<<(int)(((size_t)Fq * Hq / 4 + 255) / 256), 256>>>(outW, Wh, Wl, (size_t)Fq * Hq);
    mma_xp<<<dim3(Fq / 128, MD / 128, 1), 512, XT_SMEM_B>>>(
        Ah, Al, Wh, Wl, outB, out, MD, Fq, Hq, 0, 0, 0, 0);
}

// round 9
// speedup vs baseline: 1.3307x; 1.1973x over previous
#include <cuda_runtime.h>
#include <cuda_bf16.h>
#include <math.h>
#include <stdint.h>

#define Bq 64
#define TSq 300
#define TDq 180
#define Fq 128
#define Hq 512
#define Lq 4
#define Gq 2048   // 4*H

// ---------------- static device scratch (no runtime allocation) ----------------
__device__ float g_xp[(size_t)2 * Bq * TSq * Gq];
__device__ unsigned g_hwork[2][2 * Bq * Hq];          // packed bf16 hi|lo h state
__device__ float g_cwork[2 * Bq * Hq];
__device__ float g_hs[Lq * Bq * 1024];
__device__ float g_cs[Lq * Bq * 1024];
__device__ float g_h0[Lq * Bq * Hq];
__device__ float g_c0[Lq * Bq * Hq];
__device__ unsigned g_barSlots[16 * 32];              // 16 barrier slots, 128B apart
// bf16 split buffers for tensor-core GEMMs (activations + weights)
__device__ __nv_bfloat16 g_Ah[(size_t)Bq * TSq * 1024];
__device__ __nv_bfloat16 g_Al[(size_t)Bq * TSq * 1024];
__device__ __nv_bfloat16 g_Wh[(size_t)2 * Gq * 1024];
__device__ __nv_bfloat16 g_Wl[(size_t)2 * Gq * 1024];

// -------- mma.sync / ldmatrix / cp.async helpers (compute_103-safe) -----
__device__ __forceinline__ uint32_t smem_u32(const void* p) {
    uint32_t a;
    asm("{ .reg .u64 t; cvta.to.shared.u64 t, %1; cvt.u32.u64 %0, t; }" : "=r"(a) : "l"(p));
    return a;
}
#define LDM_X4(r0, r1, r2, r3, addr) \
    asm volatile("ldmatrix.sync.aligned.m8n8.x4.shared.b16 {%0,%1,%2,%3}, [%4];" \
        : "=r"(r0), "=r"(r1), "=r"(r2), "=r"(r3) : "r"(addr))
#define LDM_X2(r0, r1, addr) \
    asm volatile("ldmatrix.sync.aligned.m8n8.x2.shared.b16 {%0,%1}, [%2];" \
        : "=r"(r0), "=r"(r1) : "r"(addr))
#define MMA_BF16(c0, c1, c2, c3, a0, a1, a2, a3, b0, b1) \
    asm volatile("mma.sync.aligned.m16n8k16.row.col.f32.bf16.bf16.f32 " \
        "{%0,%1,%2,%3}, {%4,%5,%6,%7}, {%8,%9}, {%0,%1,%2,%3};" \
        : "+f"(c0), "+f"(c1), "+f"(c2), "+f"(c3) \
        : "r"(a0), "r"(a1), "r"(a2), "r"(a3), "r"(b0), "r"(b1))
#define CPA16(dst, src) \
    asm volatile("cp.async.cg.shared.global [%0], [%1], 16;" :: "r"(dst), "l"(src))
#define CPA_COMMIT() asm volatile("cp.async.commit_group;" ::: "memory")
#define CPA_WAIT(n)  asm volatile("cp.async.wait_group %0;" :: "n"(n) : "memory")

__device__ __forceinline__ uint32_t bf2pack(float fhi, float flo) {
    uint32_t r;
    asm("cvt.rn.bf16x2.f32 %0, %1, %2;" : "=r"(r) : "f"(fhi), "f"(flo));
    return r;
}
__device__ __forceinline__ float trunc_hi(float f) {
    return __uint_as_float(__float_as_uint(f) & 0xFFFF0000u);
}
// pack fp32 -> u32: [hi bf16 (trunc) | lo bf16 (RN residual)]
__device__ __forceinline__ unsigned packHL(float f) {
    const float lo = f - trunc_hi(f);
    unsigned lo16;
    asm("{ .reg .b16 t; cvt.rn.bf16.f32 t, %1; cvt.u32.u16 %0, t; }" : "=r"(lo16) : "f"(lo));
    return (__float_as_uint(f) & 0xFFFF0000u) | lo16;
}
__device__ __forceinline__ float unpackHL(unsigned w) {
    return __uint_as_float(w & 0xFFFF0000u) + __uint_as_float(w << 16);
}

// ---------------------------------------------------------------------------
// grid barrier on a monotonic counter: red.release arrival, ld.acquire poll.
// Counter zeroed once per kernel_launch by a captured memset.
// ---------------------------------------------------------------------------
__device__ __forceinline__ void gbar(unsigned* slot, unsigned tgt)
{
    __syncthreads();
    if (threadIdx.x == 0) {
        asm volatile("red.release.gpu.global.add.u32 [%0], 1;" :: "l"(slot) : "memory");
        unsigned v;
        while (true) {
            asm volatile("ld.acquire.gpu.global.u32 %0, [%1];" : "=r"(v) : "l"(slot) : "memory");
            if (v >= tgt) break;
            __nanosleep(32);
        }
    }
    __syncthreads();
}

// ---------------------------------------------------------------------------
// fp32 -> bf16 hi/lo split (weights / src / bridge inputs), n % 4 == 0
// ---------------------------------------------------------------------------
__global__ void conv_split(const float* __restrict__ in, __nv_bfloat16* __restrict__ hi,
                           __nv_bfloat16* __restrict__ lo, size_t n)
{
    const size_t i = ((size_t)blockIdx.x * 256 + threadIdx.x) * 4;
    if (i >= n) return;
    const float4 v = *(const float4*)(in + i);
    __nv_bfloat16 h0 = __float2bfloat16(v.x), h1 = __float2bfloat16(v.y);
    __nv_bfloat16 h2 = __float2bfloat16(v.z), h3 = __float2bfloat16(v.w);
    __nv_bfloat16 l0 = __float2bfloat16(v.x - __bfloat162float(h0));
    __nv_bfloat16 l1 = __float2bfloat16(v.y - __bfloat162float(h1));
    __nv_bfloat16 l2 = __float2bfloat16(v.z - __bfloat162float(h2));
    __nv_bfloat16 l3 = __float2bfloat16(v.w - __bfloat162float(h3));
    __nv_bfloat162 hp0(h0, h1), hp1(h2, h3), lp0(l0, l1), lp1(l2, l3);
    *(uint2*)(hi + i) = make_uint2(*(uint32_t*)&hp0, *(uint32_t*)&hp1);
    *(uint2*)(lo + i) = make_uint2(*(uint32_t*)&lp0, *(uint32_t*)&lp1);
}

// ---------------------------------------------------------------------------
// Split-bf16 tensor-core GEMM: C[M,N] = op(A[M,K] @ W[N,K]^T + b)
// D = Ah*Wh + Ah*Wl + Al*Wh. CTA 128x128, 256 threads (8 warps 2x4),
// warp tile 64x32. K chunks of 32, 3-stage cp.async, 2 CTAs/SM.
// smem rows 64B, conflict-free swizzle g ^= (row>>1)&3.
// M%128==0, N%128==0, K%32==0, K>=96.
// ---------------------------------------------------------------------------
#define XP_TILE_B   8192                     // 128x32 bf16
#define XP_STAGE_B  (4 * XP_TILE_B)          // Ah|Al|Wh|Wl = 32KB
#define XP_STAGES   3
#define XP_SMEM_B   (XP_STAGES * XP_STAGE_B) // 96KB

__global__ __launch_bounds__(256, 2)
void mma_xp(const __nv_bfloat16* __restrict__ Ah, const __nv_bfloat16* __restrict__ Al,
            const __nv_bfloat16* __restrict__ Wh, const __nv_bfloat16* __restrict__ Wl,
            const float* __restrict__ bias, float* __restrict__ C,
            int M, int N, int K, size_t wZ, size_t bZ, size_t cZ, int act)
{
    extern __shared__ __align__(128) char smem[];
    const uint32_t sbase = smem_u32(smem);

    Wh   += blockIdx.z * wZ;
    Wl   += blockIdx.z * wZ;
    bias += blockIdx.z * bZ;
    C    += blockIdx.z * cZ;
    const int n0 = blockIdx.x * 128;
    const int m0 = blockIdx.y * 128;

    const int tid  = threadIdx.x;
    const int lane = tid & 31;
    const int warp = tid >> 5;
    const int wm = warp >> 2;          // 0..1
    const int wn = warp & 3;           // 0..3

    float acc[4][4][4];
#pragma unroll
    for (int i = 0; i < 4; i++)
#pragma unroll
        for (int j = 0; j < 4; j++)
#pragma unroll
            for (int q = 0; q < 4; q++) acc[i][j][q] = 0.f;

    // cp.async mapping: 512 granules/tile, 2 rows per thread (r0, r0+64)
    const int r0 = tid >> 2, g0 = tid & 3;
    const uint32_t sw = (uint32_t)((g0 ^ ((r0 >> 1) & 3)) << 4);
    const uint32_t so0 = (uint32_t)(r0 * 64) + sw;
    const uint32_t so1 = (uint32_t)((r0 + 64) * 64) + sw;   // (r0+64)>>1 &3 == (r0>>1)&3

    // ldmatrix address components
    const int arow = wm * 64 + (lane & 15);
    const int aswz = (arow >> 1) & 3;
    const int agoff = lane >> 4;
    const int brow = wn * 32 + (lane & 7);
    const int bswz = (brow >> 1) & 3;
    const int bgoff = (lane >> 3) & 1;
    const int bnt   = lane >> 4;

    const int nch = K >> 5;

#define XPISSUE(c) do { \
    const uint32_t _buf = sbase + (uint32_t)((c) % XP_STAGES) * XP_STAGE_B; \
    const size_t _ka = (size_t)((c) << 5) + g0 * 8; \
    CPA16(_buf + 0 * XP_TILE_B + so0, Ah + (size_t)(m0 + r0) * K + _ka); \
    CPA16(_buf + 1 * XP_TILE_B + so0, Al + (size_t)(m0 + r0) * K + _ka); \
    CPA16(_buf + 2 * XP_TILE_B + so0, Wh + (size_t)(n0 + r0) * K + _ka); \
    CPA16(_buf + 3 * XP_TILE_B + so0, Wl + (size_t)(n0 + r0) * K + _ka); \
    CPA16(_buf + 0 * XP_TILE_B + so1, Ah + (size_t)(m0 + r0 + 64) * K + _ka); \
    CPA16(_buf + 1 * XP_TILE_B + so1, Al + (size_t)(m0 + r0 + 64) * K + _ka); \
    CPA16(_buf + 2 * XP_TILE_B + so1, Wh + (size_t)(n0 + r0 + 64) * K + _ka); \
    CPA16(_buf + 3 * XP_TILE_B + so1, Wl + (size_t)(n0 + r0 + 64) * K + _ka); \
} while (0)

    XPISSUE(0); CPA_COMMIT();
    XPISSUE(1); CPA_COMMIT();

    for (int c = 0; c < nch; c++) {
        if (c + 2 < nch) { XPISSUE(c + 2); CPA_COMMIT(); CPA_WAIT(2); }
        else if (c + 1 < nch) { CPA_WAIT(1); }
        else { CPA_WAIT(0); }
        __syncthreads();

        const uint32_t buf = sbase + (uint32_t)(c % XP_STAGES) * XP_STAGE_B;
        const uint32_t aH = buf + 0 * XP_TILE_B;
        const uint32_t aL = buf + 1 * XP_TILE_B;
        const uint32_t wH = buf + 2 * XP_TILE_B;
        const uint32_t wL = buf + 3 * XP_TILE_B;

#pragma unroll
        for (int ks = 0; ks < 2; ks++) {
            uint32_t af[4][4], bh[4][2], bl[4][2];
            // A-hi fragments
#pragma unroll
            for (int mt = 0; mt < 4; mt++) {
                const int rA = arow + mt * 16;
                const uint32_t ad = aH + (uint32_t)(rA * 64 + (((ks * 2 + agoff) ^ aswz) << 4));
                LDM_X4(af[mt][0], af[mt][1], af[mt][2], af[mt][3], ad);
            }
            // W-hi / W-lo fragments
#pragma unroll
            for (int p = 0; p < 2; p++) {
                const int rB = brow + (p * 2 + bnt) * 8;
                const uint32_t off = (uint32_t)(rB * 64 + (((ks * 2 + bgoff) ^ bswz) << 4));
                LDM_X4(bh[p * 2][0], bh[p * 2][1], bh[p * 2 + 1][0], bh[p * 2 + 1][1], wH + off);
                LDM_X4(bl[p * 2][0], bl[p * 2][1], bl[p * 2 + 1][0], bl[p * 2 + 1][1], wL + off);
            }
            // Ah*Wh then Ah*Wl
#pragma unroll
            for (int mt = 0; mt < 4; mt++)
#pragma unroll
                for (int nt = 0; nt < 4; nt++)
                    MMA_BF16(acc[mt][nt][0], acc[mt][nt][1], acc[mt][nt][2], acc[mt][nt][3],
                             af[mt][0], af[mt][1], af[mt][2], af[mt][3],
                             bh[nt][0], bh[nt][1]);
#pragma unroll
            for (int mt = 0; mt < 4; mt++)
#pragma unroll
                for (int nt = 0; nt < 4; nt++)
                    MMA_BF16(acc[mt][nt][0], acc[mt][nt][1], acc[mt][nt][2], acc[mt][nt][3],
                             af[mt][0], af[mt][1], af[mt][2], af[mt][3],
                             bl[nt][0], bl[nt][1]);
            // A-lo reload, Al*Wh
#pragma unroll
            for (int mt = 0; mt < 4; mt++) {
                const int rA = arow + mt * 16;
                const uint32_t ad = aL + (uint32_t)(rA * 64 + (((ks * 2 + agoff) ^ aswz) << 4));
                LDM_X4(af[mt][0], af[mt][1], af[mt][2], af[mt][3], ad);
            }
#pragma unroll
            for (int mt = 0; mt < 4; mt++)
#pragma unroll
                for (int nt = 0; nt < 4; nt++)
                    MMA_BF16(acc[mt][nt][0], acc[mt][nt][1], acc[mt][nt][2], acc[mt][nt][3],
                             af[mt][0], af[mt][1], af[mt][2], af[mt][3],
                             bh[nt][0], bh[nt][1]);
        }
        __syncthreads();
    }

    const int mE = m0 + wm * 64 + (lane >> 2);
    const int nE = n0 + wn * 32 + (lane & 3) * 2;
#pragma unroll
    for (int mt = 0; mt < 4; mt++) {
#pragma unroll
        for (int nt = 0; nt < 4; nt++) {
            const int m = mE + mt * 16;
            const int n = nE + nt * 8;
            const float b0 = bias[n], b1 = bias[n + 1];
            float v00 = acc[mt][nt][0] + b0, v01 = acc[mt][nt][1] + b1;
            float v10 = acc[mt][nt][2] + b0, v11 = acc[mt][nt][3] + b1;
            if (act) { v00 = tanhf(v00); v01 = tanhf(v01); v10 = tanhf(v10); v11 = tanhf(v11); }
            *(float2*)(C + (size_t)m * N + n)       = make_float2(v00, v01);
            *(float2*)(C + (size_t)(m + 8) * N + n) = make_float2(v10, v11);
        }
    }
}

// ---------------------------------------------------------------------------
// Persistent LSTM layer with tensor-core recurrence.
// h state: packed u32 (bf16 hi|lo). y output written DIRECTLY as bf16 hi/lo
// into the next GEMM's A buffers (yh/yl); no fp32 y, no conv_split pass.
// NBL=32: encoder (2 dirs x 64 blocks, per-dir barrier G=64);
// NBL=16: decoder (128 blocks, G=128).
// ---------------------------------------------------------------------------
template<int NBL>
__global__ __launch_bounds__(256)
void lstm_persist(const float* __restrict__ xp, const float* __restrict__ Whh,
                  const float* __restrict__ h0, const float* __restrict__ c0,
                  unsigned* __restrict__ hA, unsigned* __restrict__ hB,
                  float* __restrict__ cSt,
                  __nv_bfloat16* __restrict__ yh, __nv_bfloat16* __restrict__ yl,
                  float* __restrict__ hFin, float* __restrict__ cFin,
                  int T, int revDir1, int yStride, int yDirMult, int slotIdx)
{
    constexpr int U    = NBL / 4;
    constexpr int USH  = (NBL == 32) ? 3 : 2;
    constexpr int WNT  = NBL / 16;
    constexpr int GSs  = NBL + 2;
    constexpr unsigned G = (NBL == 32) ? 64u : 128u;
    constexpr uint32_t S_AH = 0;
    constexpr uint32_t S_AL = 64 * 1024;
    constexpr uint32_t S_BH = 128 * 1024;
    constexpr uint32_t S_BL = S_BH + NBL * 1024;
    constexpr uint32_t S_GS = S_BL + NBL * 1024;

    extern __shared__ __align__(128) char smem[];
    const uint32_t sb = smem_u32(smem);
    float* Gs = (float*)(smem + S_GS);

    const int tid  = threadIdx.x;
    const int lane = tid & 31;
    const int warp = tid >> 5;
    const int mi = warp >> 1;
    const int nh = warp & 1;

    int dir, u0;
    if (NBL == 32) { dir = blockIdx.x >> 6; u0 = (blockIdx.x & 63) * 8; }
    else           { dir = 0;               u0 = blockIdx.x * 4; }

    unsigned* slot = g_barSlots + (size_t)(slotIdx + ((NBL == 32) ? dir : 0)) * 32;
    unsigned barTgt = 0;

    const float* xpd = xp  + (size_t)dir * Bq * T * Gq;
    const float* Wd  = Whh + (size_t)dir * Gq * Hq;
    unsigned* hArr[2] = { hA + dir * Bq * Hq, hB + dir * Bq * Hq };
    float* cD = cSt + dir * Bq * Hq;

    // ---- convert Whh rows into smem bf16 hi/lo, swizzled (once) ----
    for (int i = tid; i < NBL * 64; i += 256) {
        const int row = i >> 6;
        const int g   = i & 63;
        const int gate = row / U;
        const int uu   = row & (U - 1);
        const int wrow = (gate << 9) + u0 + uu;
        const float4 va = *(const float4*)(Wd + (size_t)wrow * Hq + g * 8);
        const float4 vb = *(const float4*)(Wd + (size_t)wrow * Hq + g * 8 + 4);
        uint4 hi, lo;
        hi.x = __byte_perm(__float_as_uint(va.x), __float_as_uint(va.y), 0x7632);
        hi.y = __byte_perm(__float_as_uint(va.z), __float_as_uint(va.w), 0x7632);
        hi.z = __byte_perm(__float_as_uint(vb.x), __float_as_uint(vb.y), 0x7632);
        hi.w = __byte_perm(__float_as_uint(vb.z), __float_as_uint(vb.w), 0x7632);
        lo.x = bf2pack(va.y - trunc_hi(va.y), va.x - trunc_hi(va.x));
        lo.y = bf2pack(va.w - trunc_hi(va.w), va.z - trunc_hi(va.z));
        lo.z = bf2pack(vb.y - trunc_hi(vb.y), vb.x - trunc_hi(vb.x));
        lo.w = bf2pack(vb.w - trunc_hi(vb.w), vb.z - trunc_hi(vb.z));
        const uint32_t so = (uint32_t)(row * 1024 + ((g ^ (row & 7)) << 4));
        *(uint4*)(smem + S_BH + so) = hi;
        *(uint4*)(smem + S_BL + so) = lo;
    }

    // ---- init h (packed), c ----
    for (int i = tid; i < Bq * U; i += 256) {
        const int b = i >> USH, uu = i & (U - 1), u = u0 + uu;
        hArr[0][b * Hq + u] = h0 ? packHL(h0[b * Hq + u]) : 0u;
        cD        [b * Hq + u] = c0 ? c0[b * Hq + u] : 0.f;
    }
    barTgt += G; gbar(slot, barTgt);

    const int rowA = (lane & 15);
    const int agoff = lane >> 4;
    const int bnt   = lane >> 4;
    const int bgoff = (lane >> 3) & 1;

    int ping = 0;
    for (int t = 0; t < T; t++) {
        const int tt = (dir == 1 && revDir1) ? (T - 1 - t) : t;
        const unsigned* hI = hArr[ping];
        unsigned*       hO = hArr[ping ^ 1];

        // ---- stage packed h -> smem hi/lo granules (PRMT only) ----
#pragma unroll
        for (int it = 0; it < 16; it++) {
            const int slotI = tid + it * 256;
            const int row = slotI >> 6, g = slotI & 63;
            const uint4* p = (const uint4*)(hI + (size_t)row * Hq + g * 8);
            const uint4 v0 = __ldcg(p);
            const uint4 v1 = __ldcg(p + 1);
            uint4 hi, lo;
            hi.x = __byte_perm(v0.x, v0.y, 0x7632); hi.y = __byte_perm(v0.z, v0.w, 0x7632);
            hi.z = __byte_perm(v1.x, v1.y, 0x7632); hi.w = __byte_perm(v1.z, v1.w, 0x7632);
            lo.x = __byte_perm(v0.x, v0.y, 0x5410); lo.y = __byte_perm(v0.z, v0.w, 0x5410);
            lo.z = __byte_perm(v1.x, v1.y, 0x5410); lo.w = __byte_perm(v1.z, v1.w, 0x5410);
            const uint32_t so = (uint32_t)(row * 1024 + ((g ^ (row & 7)) << 4));
            *(uint4*)(smem + S_AH + so) = hi;
            *(uint4*)(smem + S_AL + so) = lo;
        }
        __syncthreads();

        float acc[WNT][4];
#pragma unroll
        for (int nt = 0; nt < WNT; nt++)
#pragma unroll
            for (int q = 0; q < 4; q++) acc[nt][q] = 0.f;

#pragma unroll 4
        for (int ks = 0; ks < 32; ks++) {
            const int rA = mi * 16 + rowA;
            const uint32_t aoff = (uint32_t)(rA * 1024 + (((ks * 2 + agoff) ^ (rA & 7)) << 4));
            uint32_t ah[4], al[4], bh[2 * WNT], bl[2 * WNT];
            LDM_X4(ah[0], ah[1], ah[2], ah[3], sb + S_AH + aoff);
            LDM_X4(al[0], al[1], al[2], al[3], sb + S_AL + aoff);
            if (WNT == 2) {
                const int rB = nh * 16 + bnt * 8 + (lane & 7);
                const uint32_t boff = (uint32_t)(rB * 1024 + (((ks * 2 + bgoff) ^ (rB & 7)) << 4));
                LDM_X4(bh[0], bh[1], bh[2], bh[3], sb + S_BH + boff);
                LDM_X4(bl[0], bl[1], bl[2], bl[3], sb + S_BL + boff);
            } else {
                const int rB = nh * 8 + (lane & 7);
                const uint32_t boff = (uint32_t)(rB * 1024 + (((ks * 2 + bgoff) ^ (rB & 7)) << 4));
                LDM_X2(bh[0], bh[1], sb + S_BH + boff);
                LDM_X2(bl[0], bl[1], sb + S_BL + boff);
            }
#pragma unroll
            for (int nt = 0; nt < WNT; nt++)
                MMA_BF16(acc[nt][0], acc[nt][1], acc[nt][2], acc[nt][3],
                         ah[0], ah[1], ah[2], ah[3], bh[nt * 2], bh[nt * 2 + 1]);
#pragma unroll
            for (int nt = 0; nt < WNT; nt++)
                MMA_BF16(acc[nt][0], acc[nt][1], acc[nt][2], acc[nt][3],
                         ah[0], ah[1], ah[2], ah[3], bl[nt * 2], bl[nt * 2 + 1]);
#pragma unroll
            for (int nt = 0; nt < WNT; nt++)
                MMA_BF16(acc[nt][0], acc[nt][1], acc[nt][2], acc[nt][3],
                         al[0], al[1], al[2], al[3], bh[nt * 2], bh[nt * 2 + 1]);
        }

        {
            const int gr  = lane >> 2;
            const int gcq = (lane & 3) * 2;
            const int m = mi * 16 + gr;
#pragma unroll
            for (int nt = 0; nt < WNT; nt++) {
                const int gc = nh * (WNT * 8) + nt * 8 + gcq;
                *(float2*)&Gs[m * GSs + gc]       = make_float2(acc[nt][0], acc[nt][1]);
                *(float2*)&Gs[(m + 8) * GSs + gc] = make_float2(acc[nt][2], acc[nt][3]);
            }
        }
        __syncthreads();

#pragma unroll
        for (int i = tid; i < Bq * U; i += 256) {
            const int b = i >> USH, uu = i & (U - 1);
            const int u = u0 + uu;
            const size_t xb = ((size_t)b * T + tt) * Gq + u;
            const float iv = Gs[b * GSs + 0 * U + uu] + xpd[xb];
            const float fv = Gs[b * GSs + 1 * U + uu] + xpd[xb + 512];
            const float gv = Gs[b * GSs + 2 * U + uu] + xpd[xb + 1024];
            const float ov = Gs[b * GSs + 3 * U + uu] + xpd[xb + 1536];
            const float cOld = cD[b * Hq + u];
            const float si = 1.f / (1.f + expf(-iv));
            const float sf = 1.f / (1.f + expf(-fv));
            const float so = 1.f / (1.f + expf(-ov));
            const float cN = sf * cOld + si * tanhf(gv);
            const float hN = so * tanhf(cN);
            const unsigned w = packHL(hN);
            cD[b * Hq + u] = cN;
            hO[b * Hq + u] = w;
            if (yh) {
                const size_t yi = ((size_t)b * T + tt) * yStride + dir * yDirMult + u;
                ((unsigned short*)yh)[yi] = (unsigned short)(w >> 16);
                ((unsigned short*)yl)[yi] = (unsigned short)(w & 0xFFFFu);
            }
        }

        if (t + 1 < T) { barTgt += G; gbar(slot, barTgt); }
        ping ^= 1;
    }

    if (hFin) {
        for (int i = tid; i < Bq * U; i += 256) {
            const int b = i >> USH, uu = i & (U - 1), u = u0 + uu;
            hFin[b * 1024 + dir * 512 + u] = unpackHL(hArr[ping][b * Hq + u]);
            cFin[b * 1024 + dir * 512 + u] = cD[b * Hq + u];
        }
    }
}

#define SMEM_ENC (128 * 1024 + 2 * 32 * 1024 + 64 * 34 * 4)
#define SMEM_DEC (128 * 1024 + 2 * 16 * 1024 + 64 * 18 * 4)

// decoder input: concat(tgt_in, sc_emb[scenario[b]]) -> bf16 hi/lo directly
__global__ void build_dcat(const float* __restrict__ tgt, const float* __restrict__ scEmb,
                           const int* __restrict__ scen,
                           __nv_bfloat16* __restrict__ oh, __nv_bfloat16* __restrict__ ol)
{
    const size_t i = (size_t)blockIdx.x * 256 + threadIdx.x;
    if (i >= (size_t)Bq * TDq * 640) return;
    const int r = (int)(i / 640);
    const int j = (int)(i - (size_t)r * 640);
    float v;
    if (j < 128) v = tgt[(size_t)r * 128 + j];
    else         v = scEmb[scen[r / TDq] * 512 + (j - 128)];
    const unsigned w = packHL(v);
    ((unsigned short*)oh)[i] = (unsigned short)(w >> 16);
    ((unsigned short*)ol)[i] = (unsigned short)(w & 0xFFFFu);
}

// ---------------------------------------------------------------------------
extern "C" void kernel_launch(void* const* d_in, const int* in_sizes, int n_in,
                              void* d_out, int out_size)
{
    (void)in_sizes; (void)n_in; (void)out_size;
    const float* src   = (const float*)d_in[0];
    const float* tgt   = (const float*)d_in[1];
    const int*   scen  = (const int*)  d_in[2];
    const float* eWih0 = (const float*)d_in[3];
    const float* eWhh0 = (const float*)d_in[4];
    const float* eB0   = (const float*)d_in[5];
    const float* eWih  = (const float*)d_in[6];
    const float* eWhh  = (const float*)d_in[7];
    const float* eB    = (const float*)d_in[8];
    const float* hbW   = (const float*)d_in[9];
    const float* hbB   = (const float*)d_in[10];
    const float* cbW   = (const float*)d_in[11];
    const float* cbB   = (const float*)d_in[12];
    const float* scEmb = (const float*)d_in[13];
    const float* dWih0 = (const float*)d_in[14];
    const float* dWhh0 = (const float*)d_in[15];
    const float* dB0   = (const float*)d_in[16];
    const float* dWih  = (const float*)d_in[17];
    const float* dWhh  = (const float*)d_in[18];
    const float* dB    = (const float*)d_in[19];
    const float* outW  = (const float*)d_in[20];
    const float* outB  = (const float*)d_in[21];
    float* out = (float*)d_out;

    float *xp, *cst, *hsP, *csP, *h0P, *c0P;
    unsigned *hwork, *barP;
    __nv_bfloat16 *Ah, *Al, *Wh, *Wl;
    cudaGetSymbolAddress((void**)&xp,    g_xp);
    cudaGetSymbolAddress((void**)&hwork, g_hwork);
    cudaGetSymbolAddress((void**)&cst,   g_cwork);
    cudaGetSymbolAddress((void**)&hsP,   g_hs);
    cudaGetSymbolAddress((void**)&csP,   g_cs);
    cudaGetSymbolAddress((void**)&h0P,   g_h0);
    cudaGetSymbolAddress((void**)&c0P,   g_c0);
    cudaGetSymbolAddress((void**)&barP,  g_barSlots);
    cudaGetSymbolAddress((void**)&Ah,    g_Ah);
    cudaGetSymbolAddress((void**)&Al,    g_Al);
    cudaGetSymbolAddress((void**)&Wh,    g_Wh);
    cudaGetSymbolAddress((void**)&Wl,    g_Wl);
    unsigned* hA = hwork;
    unsigned* hB = hwork + 2 * Bq * Hq;

    cudaFuncSetAttribute(lstm_persist<32>, cudaFuncAttributeMaxDynamicSharedMemorySize, SMEM_ENC);
    cudaFuncSetAttribute(lstm_persist<16>, cudaFuncAttributeMaxDynamicSharedMemorySize, SMEM_DEC);
    cudaFuncSetAttribute(mma_xp, cudaFuncAttributeMaxDynamicSharedMemorySize, XP_SMEM_B);

    const int ME = Bq * TSq;   // 19200
    const int MD = Bq * TDq;   // 11520

    // reset barrier counters (one captured memset per launch)
    cudaMemsetAsync(barP, 0, 16 * 32 * sizeof(unsigned), 0);

    // ======================= encoder =======================
    // layer-0 input: split src once
    conv_split<<<(int)(((size_t)ME * Fq / 4 + 255) / 256), 256>>>(src, Ah, Al, (size_t)ME * Fq);

    int inDim = Fq;
    for (int l = 0; l < Lq; l++) {
        const float* Wih = l ? eWih + (size_t)(l - 1) * 2 * Gq * 1024 : eWih0;
        const float* bih = l ? eB   + (size_t)(l - 1) * 2 * Gq        : eB0;

        const size_t nW = (size_t)2 * Gq * inDim;
        conv_split<<<(int)((nW / 4 + 255) / 256), 256>>>(Wih, Wh, Wl, nW);
        mma_xp<<<dim3(Gq / 128, ME / 128, 2), 256, XP_SMEM_B>>>(
            Ah, Al, Wh, Wl, bih, xp, ME, Gq, inDim,
            (size_t)Gq * inDim, (size_t)Gq, (size_t)ME * Gq, 0);

        const float* Whh = l ? eWhh + (size_t)(l - 1) * 2 * Gq * Hq : eWhh0;
        const int lastEnc = (l == Lq - 1);
        lstm_persist<32><<<128, 256, SMEM_ENC>>>(
            xp, Whh, nullptr, nullptr, hA, hB, cst,
            lastEnc ? nullptr : Ah, lastEnc ? nullptr : Al,
            hsP + (size_t)l * Bq * 1024, csP + (size_t)l * Bq * 1024,
            TSq, 1, 1024, 512, 2 * l);

        inDim = 1024;
    }

    // ======================= bridges (tanh, tensor cores) =======================
    conv_split<<<(int)(((size_t)Lq * Bq * 1024 / 4 + 255) / 256), 256>>>(hsP, Ah, Al, (size_t)Lq * Bq * 1024);
    conv_split<<<(int)(((size_t)Hq * 1024 / 4 + 255) / 256), 256>>>(hbW, Wh, Wl, (size_t)Hq * 1024);
    mma_xp<<<dim3(Hq / 128, (Lq * Bq) / 128, 1), 256, XP_SMEM_B>>>(
        Ah, Al, Wh, Wl, hbB, h0P, Lq * Bq, Hq, 1024, 0, 0, 0, 1);
    conv_split<<<(int)(((size_t)Lq * Bq * 1024 / 4 + 255) / 256), 256>>>(csP, Ah, Al, (size_t)Lq * Bq * 1024);
    conv_split<<<(int)(((size_t)Hq * 1024 / 4 + 255) / 256), 256>>>(cbW, Wh, Wl, (size_t)Hq * 1024);
    mma_xp<<<dim3(Hq / 128, (Lq * Bq) / 128, 1), 256, XP_SMEM_B>>>(
        Ah, Al, Wh, Wl, cbB, c0P, Lq * Bq, Hq, 1024, 0, 0, 0, 1);

    // ======================= decoder =======================
    build_dcat<<<(int)(((size_t)Bq * TDq * 640 + 255) / 256), 256>>>(tgt, scEmb, scen, Ah, Al);

    inDim = Fq + Hq;   // 640
    for (int l = 0; l < Lq; l++) {
        const float* Wih = l ? dWih + (size_t)(l - 1) * Gq * Hq : dWih0;
        const float* bih = l ? dB   + (size_t)(l - 1) * Gq      : dB0;

        const size_t nW = (size_t)Gq * inDim;
        conv_split<<<(int)((nW / 4 + 255) / 256), 256>>>(Wih, Wh, Wl, nW);
        mma_xp<<<dim3(Gq / 128, MD / 128, 1), 256, XP_SMEM_B>>>(
            Ah, Al, Wh, Wl, bih, xp, MD, Gq, inDim, 0, 0, 0, 0);

        const float* Whh = l ? dWhh + (size_t)(l - 1) * Gq * Hq : dWhh0;
        lstm_persist<16><<<128, 256, SMEM_DEC>>>(
            xp, Whh, h0P + (size_t)l * Bq * Hq, c0P + (size_t)l * Bq * Hq,
            hA, hB, cst, Ah, Al, nullptr, nullptr,
            TDq, 0, 512, 0, 8 + l);

        inDim = Hq;
    }

    // output projection (tensor cores) straight into d_out
    conv_split<<<(int)(((size_t)Fq * Hq / 4 + 255) / 256), 256>>>(outW, Wh, Wl, (size_t)Fq * Hq);
    mma_xp<<<dim3(Fq / 128, MD / 128, 1), 256, XP_SMEM_B>>>(
        Ah, Al, Wh, Wl, outB, out, MD, Fq, Hq, 0, 0, 0, 0);
}